// round 9
// baseline (speedup 1.0000x reference)
#include <cuda_runtime.h>
#include <cuda_bf16.h>
#include <cstdint>

#define Bdim 8
#define Ndim 1024
#define Tdim 64
#define TOTAL (Bdim*Ndim*Tdim)

typedef unsigned long long u64t;

// scratch (static device memory)
__device__ float g_S[Ndim * 1024];    // K-split half 0
__device__ float g_S2[Ndim * 1024];   // K-split half 1
__device__ float g_cs[Ndim];
__device__ float g_C[6 * 64];
__device__ float g_beta[64];
__device__ float g_gamma[6];
__device__ float g_knots[127];
__device__ float g_slope[65];
__device__ float g_inter[65];
// pre-split bf16 operands: [k][col] row-major, 1024 cols (pairs packed in u32)
__device__ __align__(16) uint32_t g_Ahi[1024 * 512];
__device__ __align__(16) uint32_t g_Alo[1024 * 512];
__device__ __align__(16) uint32_t g_Bhi[1024 * 512];
__device__ __align__(16) uint32_t g_Blo[1024 * 512];

// ------------------------------ helpers -----------------------------------
__device__ __forceinline__ uint32_t smem_u32(const void* p) {
    uint32_t a;
    asm("{ .reg .u64 t; cvta.to.shared.u64 t, %1; cvt.u32.u64 %0, t; }"
        : "=r"(a) : "l"(p));
    return a;
}
__device__ __forceinline__ uint32_t pack_bf16x2(float lo, float hi) {
    uint32_t r;
    asm("cvt.rn.bf16x2.f32 %0, %1, %2;" : "=r"(r) : "f"(hi), "f"(lo));
    return r;
}
__device__ __forceinline__ void ldsm_x4_t(uint32_t& r0, uint32_t& r1,
                                          uint32_t& r2, uint32_t& r3,
                                          uint32_t addr) {
    asm volatile("ldmatrix.sync.aligned.m8n8.x4.trans.shared.b16 "
                 "{%0,%1,%2,%3}, [%4];"
                 : "=r"(r0), "=r"(r1), "=r"(r2), "=r"(r3) : "r"(addr));
}
__device__ __forceinline__ void mma16816(float* c, const uint32_t* a,
                                         const uint32_t* b) {
    asm volatile(
        "mma.sync.aligned.m16n8k16.row.col.f32.bf16.bf16.f32 "
        "{%0,%1,%2,%3}, {%4,%5,%6,%7}, {%8,%9}, {%0,%1,%2,%3};"
        : "+f"(c[0]), "+f"(c[1]), "+f"(c[2]), "+f"(c[3])
        : "r"(a[0]), "r"(a[1]), "r"(a[2]), "r"(a[3]), "r"(b[0]), "r"(b[1]));
}
__device__ __forceinline__ void cp16(uint32_t dst, const void* src) {
    asm volatile("cp.async.cg.shared.global [%0], [%1], 16;"
                 :: "r"(dst), "l"(src) : "memory");
}
// packed f32x2 ops (Blackwell base ISA)
__device__ __forceinline__ u64t fma2(u64t a, u64t b, u64t c) {
    u64t d;
    asm("fma.rn.f32x2 %0, %1, %2, %3;" : "=l"(d) : "l"(a), "l"(b), "l"(c));
    return d;
}
__device__ __forceinline__ u64t add2(u64t a, u64t b) {
    u64t d;
    asm("add.rn.f32x2 %0, %1, %2;" : "=l"(d) : "l"(a), "l"(b));
    return d;
}
__device__ __forceinline__ u64t abs2(u64t a) {
    u64t d;
    asm("and.b64 %0, %1, 0x7FFFFFFF7FFFFFFF;" : "=l"(d) : "l"(a));
    return d;
}
__device__ __forceinline__ u64t pack2(float lo, float hi) {
    u64t d;
    asm("mov.b64 %0, {%1, %2};" : "=l"(d) : "f"(lo), "f"(hi));
    return d;
}
__device__ __forceinline__ void unpack2(float& lo, float& hi, u64t v) {
    asm("mov.b64 {%0, %1}, %2;" : "=f"(lo), "=f"(hi) : "l"(v));
}

// ---------------------------------------------------------------------------
// Kernel 1: coefficient folding + PW-linear MLP tables + zero g_cs.
// ---------------------------------------------------------------------------
__global__ void coeff_kernel(const float* __restrict__ W_in,
                             const float* __restrict__ b_in,
                             const float* __restrict__ W_gc,
                             const float* __restrict__ b_gc,
                             const float* __restrict__ W_lo,
                             const float* __restrict__ b_lo,
                             const float* __restrict__ prelu_a,
                             const float* __restrict__ W_ro,
                             const float* __restrict__ b_ro,
                             const float* __restrict__ W_o1,
                             const float* __restrict__ b_o1,
                             const float* __restrict__ W_o2,
                             const float* __restrict__ b_o2) {
    __shared__ float w0[64], w1[64], bi[64];
    __shared__ float A[6][64];
    __shared__ float sC[6][64];
    __shared__ float sAl[64];
    __shared__ float kno[64], srt[64];
    __shared__ int   srank[64];
    __shared__ float sw1[64], sb1[64], sw2[64];
    int t = threadIdx.x;

    if (t < 64) {
        w0[t] = W_in[t * 66 + 0];
        w1[t] = W_in[t * 66 + 1];
        bi[t] = b_in[t];
    }
    __syncthreads();
    if (t < 64) {
        float a0 = 0.f, a1 = 0.f, a2 = 0.f, a3 = 0.f, a4 = 0.f, a5 = 0.f;
        for (int k = 0; k < 64; k++) {
            float g1 = W_gc[t * 128 + k];
            float g2 = W_gc[t * 128 + 64 + k];
            a0 = fmaf(g1, w0[k], a0); a1 = fmaf(g1, w1[k], a1);
            a5 = fmaf(g1, bi[k], a5);
            a2 = fmaf(g2, w0[k], a2); a3 = fmaf(g2, w1[k], a3);
            a4 = fmaf(g2, bi[k], a4);
        }
        A[0][t] = a0; A[1][t] = a1; A[2][t] = a2;
        A[3][t] = a3; A[4][t] = a4; A[5][t] = a5 + b_gc[t];
    }
    __syncthreads();
    if (t < 64) {
        float c[6] = {0.f, 0.f, 0.f, 0.f, 0.f, 0.f};
        for (int k = 0; k < 64; k++) {
            float wl = W_lo[t * 128 + k];
            #pragma unroll
            for (int i = 0; i < 6; i++) c[i] = fmaf(wl, A[i][k], c[i]);
        }
        c[5] += b_lo[t];
        #pragma unroll
        for (int i = 0; i < 6; i++) { sC[i][t] = c[i]; g_C[i * 64 + t] = c[i]; }
        float a = prelu_a[0];
        float wr = W_ro[t];
        sAl[t] = wr * 0.5f * (1.f + a);
        g_beta[t] = wr * 0.5f * (1.f - a);
        sw1[t] = W_o1[t]; sb1[t] = b_o1[t]; sw2[t] = W_o2[t];
    }
    __syncthreads();
    if (t < 6) {
        float g = 0.f;
        for (int k = 0; k < 64; k++) g = fmaf(sAl[k], sC[t][k], g);
        if (t == 5) g += b_ro[0];
        g_gamma[t] = g;
    }
    if (t < 64) {
        float w = sw1[t];
        kno[t] = (w != 0.f) ? (-sb1[t] / w) : 3.0e38f;
    }
    __syncthreads();
    if (t < 64) {
        float kt = kno[t];
        int r = 0;
        for (int j = 0; j < 64; j++)
            r += (kno[j] < kt) || (kno[j] == kt && j < t);
        srank[t] = r;
        srt[r] = kt;
    }
    __syncthreads();
    if (t < 64) g_knots[t] = srt[t];
    for (int i = 64 + t; i < 127; i += blockDim.x) g_knots[i] = 3.2e38f;
    if (t < 65) {
        float sl = 0.f, in = b_o2[0];
        for (int f = 0; f < 64; f++) {
            float w = sw1[f], w2 = sw2[f];
            if (w > 0.f) {
                if (srank[f] < t) { sl = fmaf(w2, w, sl); in = fmaf(w2, sb1[f], in); }
            } else if (w < 0.f) {
                if (srank[f] >= t) { sl = fmaf(w2, w, sl); in = fmaf(w2, sb1[f], in); }
            } else {
                in = fmaf(w2, fmaxf(sb1[f], 0.f), in);
            }
        }
        g_slope[t] = sl; g_inter[t] = in;
    }
    for (int i = t; i < Ndim; i += blockDim.x) g_cs[i] = 0.f;
}

// ---------------------------------------------------------------------------
// Kernel 2: split adj and R=(x1|mask) into bf16 hi/lo. grid 1024 x 256.
// ---------------------------------------------------------------------------
__global__ void prep_kernel(const float* __restrict__ adj,
                            const float* __restrict__ x,
                            const int*   __restrict__ mask,
                            const float* __restrict__ b_fs) {
    const int k = blockIdx.x;
    const int t = threadIdx.x;
    const float bfs0 = b_fs[0];

    float4 a = *(const float4*)(adj + k * 1024 + t * 4);
    uint32_t ux = __float_as_uint(a.x), uy = __float_as_uint(a.y);
    uint32_t uz = __float_as_uint(a.z), uw = __float_as_uint(a.w);
    uint2 hi, lo;
    hi.x = __byte_perm(ux, uy, 0x7632);
    hi.y = __byte_perm(uz, uw, 0x7632);
    lo.x = pack_bf16x2(a.x - __uint_as_float(ux & 0xFFFF0000u),
                       a.y - __uint_as_float(uy & 0xFFFF0000u));
    lo.y = pack_bf16x2(a.z - __uint_as_float(uz & 0xFFFF0000u),
                       a.w - __uint_as_float(uw & 0xFFFF0000u));
    *(uint2*)&g_Ahi[k * 512 + t * 2] = hi;
    *(uint2*)&g_Alo[k * 512 + t * 2] = lo;

    int j = 2 * t;
    int b = j >> 6, tt = j & 63;
    int gi = b * 65536 + k * 64 + tt;
    int m0 = mask[gi], m1 = mask[gi + 1];
    float v0 = m0 ? x[gi] : bfs0;
    float v1 = m1 ? x[gi + 1] : bfs0;
    uint32_t u0 = __float_as_uint(v0), u1 = __float_as_uint(v1);
    g_Bhi[k * 512 + t] = __byte_perm(u0, u1, 0x7632);
    g_Blo[k * 512 + t] = pack_bf16x2(v0 - __uint_as_float(u0 & 0xFFFF0000u),
                                     v1 - __uint_as_float(u1 & 0xFFFF0000u));
    g_Bhi[k * 512 + 256 + t] = pack_bf16x2((float)m0, (float)m1);
    g_Blo[k * 512 + 256 + t] = 0u;
}

// ---------------------------------------------------------------------------
// Kernel 3: column sums of adj. 128 blocks x 256.
// ---------------------------------------------------------------------------
__global__ void colsum_kernel(const float* __restrict__ adj) {
    int m = (blockIdx.x & 3) * 256 + threadIdx.x;
    int n0 = (blockIdx.x >> 2) * 32;
    float s = 0.f;
    #pragma unroll 8
    for (int n = n0; n < n0 + 32; n++)
        s += adj[n * Ndim + m];
    atomicAdd(&g_cs[m], s);
}

// ---------------------------------------------------------------------------
// Kernel 4: bf16 split-GEMM, 4-stage cp.async pipeline, ONE sync/iter.
//   CTA: D[128 m, 64 j] over K=512; K-chunk 32.
//   grid (16 j, 8 m, 2 ksplit) = 256 CTAs, 256 threads, 2 CTAs/SM.
//   Stage order per iter: wait -> barrier -> issue(it+3) -> compute(it).
//   The stage issue(it+3) overwrites was last read by compute(it-1), which
//   the barrier has already fenced.
// ---------------------------------------------------------------------------
#define A_STRIDE_B 272
#define B_STRIDE_B 144
#define ST_AHI 0
#define ST_ALO 8704
#define ST_BHI 17408
#define ST_BLO 22016
#define STAGE_STRIDE 26624
#define NSTAGE 4
#define GEMM_SMEM (NSTAGE * STAGE_STRIDE)   // 106496

__global__ void __launch_bounds__(256, 2)
gemm_mma_kernel() {
    extern __shared__ __align__(16) char smp[];
    const uint32_t sb = smem_u32(smp);

    const int tid  = threadIdx.x;
    const int lane = tid & 31;
    const int wid  = tid >> 5;
    const int warp_m = (wid & 3) * 32;
    const int warp_j = (wid >> 2) * 32;
    const int mcta = blockIdx.y * 128;
    const int bx   = blockIdx.x;
    const int j0   = bx * 64;
    const int kbase = blockIdx.z * 512;
    const bool isMask = (bx >= 8);

    // ldmatrix per-lane addresses (validated mapping)
    const int aK = (lane & 7) + ((lane & 16) ? 8 : 0);
    const int aM = (lane & 8) ? 8 : 0;
    const int bK = (lane & 7) + ((lane & 8) ? 8 : 0);
    const int bJ = (lane & 16) ? 8 : 0;
    const uint32_t aBase = sb + ST_AHI + (uint32_t)(aK * A_STRIDE_B + (warp_m + aM) * 2);
    const uint32_t bBase = sb + ST_BHI + (uint32_t)(bK * B_STRIDE_B + (warp_j + bJ) * 2);

    float acc[2][4][4];
    #pragma unroll
    for (int mt = 0; mt < 2; mt++)
        #pragma unroll
        for (int nt = 0; nt < 4; nt++)
            #pragma unroll
            for (int r = 0; r < 4; r++) acc[mt][nt][r] = 0.f;

    // cp.async geometry for K-chunk 32
    const int arow = tid >> 4, acol = tid & 15;
    const int brow = tid >> 3, bcol = tid & 7;

    auto issue_chunk = [&](int it) {
        const int s = it & (NSTAGE - 1);
        const int k0 = kbase + it * 32;
        const uint32_t stg = sb + s * STAGE_STRIDE;
        #pragma unroll
        for (int i = 0; i < 2; i++) {
            int row = arow + i * 16;
            uint32_t doff = row * A_STRIDE_B + acol * 16;
            size_t goff = (size_t)(k0 + row) * 2048 + mcta * 2 + acol * 16;
            cp16(stg + ST_AHI + doff, (const char*)g_Ahi + goff);
            cp16(stg + ST_ALO + doff, (const char*)g_Alo + goff);
        }
        {
            uint32_t doff = brow * B_STRIDE_B + bcol * 16;
            size_t goff = (size_t)(k0 + brow) * 2048 + j0 * 2 + bcol * 16;
            cp16(stg + ST_BHI + doff, (const char*)g_Bhi + goff);
            if (!isMask)
                cp16(stg + ST_BLO + doff, (const char*)g_Blo + goff);
        }
        asm volatile("cp.async.commit_group;" ::: "memory");
    };

    auto compute = [&](int s) {
        const uint32_t aS = aBase + s * STAGE_STRIDE;
        const uint32_t bS = bBase + s * STAGE_STRIDE;
        #pragma unroll
        for (int ks = 0; ks < 2; ks++) {
            uint32_t aKaddr = aS + ks * (16 * A_STRIDE_B);
            uint32_t bKaddr = bS + ks * (16 * B_STRIDE_B);
            uint32_t ah[2][4], al[2][4], bh[2][4], bl[2][4];
            ldsm_x4_t(ah[0][0], ah[0][1], ah[0][2], ah[0][3], aKaddr);
            ldsm_x4_t(ah[1][0], ah[1][1], ah[1][2], ah[1][3], aKaddr + 32);
            ldsm_x4_t(al[0][0], al[0][1], al[0][2], al[0][3], aKaddr + (ST_ALO - ST_AHI));
            ldsm_x4_t(al[1][0], al[1][1], al[1][2], al[1][3], aKaddr + (ST_ALO - ST_AHI) + 32);
            ldsm_x4_t(bh[0][0], bh[0][1], bh[0][2], bh[0][3], bKaddr);
            ldsm_x4_t(bh[1][0], bh[1][1], bh[1][2], bh[1][3], bKaddr + 32);
            if (!isMask) {
                ldsm_x4_t(bl[0][0], bl[0][1], bl[0][2], bl[0][3], bKaddr + (ST_BLO - ST_BHI));
                ldsm_x4_t(bl[1][0], bl[1][1], bl[1][2], bl[1][3], bKaddr + (ST_BLO - ST_BHI) + 32);
            }
            #pragma unroll
            for (int mt = 0; mt < 2; mt++)
                #pragma unroll
                for (int nt = 0; nt < 4; nt++) {
                    const uint32_t* Bh = &bh[nt >> 1][(nt & 1) * 2];
                    mma16816(acc[mt][nt], ah[mt], Bh);
                    mma16816(acc[mt][nt], al[mt], Bh);
                    if (!isMask) {
                        const uint32_t* Bl = &bl[nt >> 1][(nt & 1) * 2];
                        mma16816(acc[mt][nt], ah[mt], Bl);
                    }
                }
        }
    };

    issue_chunk(0);
    issue_chunk(1);
    issue_chunk(2);
    for (int it = 0; it < 16; ++it) {
        if (it < 14)      asm volatile("cp.async.wait_group 2;" ::: "memory");
        else if (it == 14) asm volatile("cp.async.wait_group 1;" ::: "memory");
        else               asm volatile("cp.async.wait_group 0;" ::: "memory");
        __syncthreads();
        if (it < 13) issue_chunk(it + 3);
        compute(it & (NSTAGE - 1));
    }

    // epilogue
    float* dstbuf = blockIdx.z ? g_S2 : g_S;
    const int gid = lane >> 2, tig = lane & 3;
    const int jw = j0 + warp_j + 2 * tig;
    #pragma unroll
    for (int mt = 0; mt < 2; mt++) {
        int m = mcta + warp_m + mt * 16 + gid;
        #pragma unroll
        for (int nt = 0; nt < 4; nt++) {
            int j = jw + nt * 8;
            *(float2*)&dstbuf[m * 1024 + j] =
                make_float2(acc[mt][nt][0], acc[mt][nt][1]);
            *(float2*)&dstbuf[(m + 8) * 1024 + j] =
                make_float2(acc[mt][nt][2], acc[mt][nt][3]);
        }
    }
}

// ---------------------------------------------------------------------------
// Kernel 5: per-element tail, packed f32x2, E=8. 256 blocks x 256.
// ---------------------------------------------------------------------------
__global__ void __launch_bounds__(256)
final_kernel(const float* __restrict__ x,
             const int*   __restrict__ mask,
             const float* __restrict__ b_fs,
             float* __restrict__ out) {
    __shared__ u64t pc0[64], pc1[64], pc2[64], pc3[64], pc4[64], pc5[64], pbt[64];
    __shared__ float skn[127], ssl[65], sit[65];
    __shared__ u64t pg[6];
    int t = threadIdx.x;
    if (t < 64) {
        float c;
        c = g_C[t];       pc0[t] = pack2(c, c);
        c = g_C[64 + t];  pc1[t] = pack2(c, c);
        c = g_C[128 + t]; pc2[t] = pack2(c, c);
        c = g_C[192 + t]; pc3[t] = pack2(c, c);
        c = g_C[256 + t]; pc4[t] = pack2(c, c);
        c = g_C[320 + t]; pc5[t] = pack2(c, c);
        c = g_beta[t];    pbt[t] = pack2(c, c);
    }
    if (t < 127) skn[t] = g_knots[t];
    if (t < 65) { ssl[t] = g_slope[t]; sit[t] = g_inter[t]; }
    if (t < 6) { float g = g_gamma[t]; pg[t] = pack2(g, g); }
    __syncthreads();

    const float bfs0 = b_fs[0];
    const int base = blockIdx.x * 2048 + t;

    float x1[8], mf[8], s1[8], s2[8], csv[8];
    #pragma unroll
    for (int e = 0; e < 8; e++) {
        int idx = base + e * 256;
        int mi = mask[idx];
        float xv = x[idx];
        mf[e] = (float)mi;
        x1[e] = mi ? xv : bfs0;
        int n = (idx >> 6) & (Ndim - 1);
        int b = idx >> 16;
        int tt = idx & 63;
        int j = (b << 6) | tt;
        s1[e] = g_S[n * 1024 + j] + g_S2[n * 1024 + j];
        s2[e] = g_S[n * 1024 + 512 + j] + g_S2[n * 1024 + 512 + j];
        csv[e] = g_cs[n];
    }

    u64t X1[4], MF[4], S1[4], S2[4], CS[4], ACC[4];
    #pragma unroll
    for (int i = 0; i < 4; i++) {
        X1[i] = pack2(x1[2 * i], x1[2 * i + 1]);
        MF[i] = pack2(mf[2 * i], mf[2 * i + 1]);
        S1[i] = pack2(s1[2 * i], s1[2 * i + 1]);
        S2[i] = pack2(s2[2 * i], s2[2 * i + 1]);
        CS[i] = pack2(csv[2 * i], csv[2 * i + 1]);
        ACC[i] = 0ull;
    }

    #pragma unroll 4
    for (int o = 0; o < 64; o++) {
        u64t K0 = pc0[o], K1 = pc1[o], K2 = pc2[o], K3 = pc3[o];
        u64t K4 = pc4[o], K5 = pc5[o], BT = pbt[o];
        #pragma unroll
        for (int i = 0; i < 4; i++) {
            u64t v = fma2(K4, CS[i], K5);
            v = fma2(K1, MF[i], v);
            v = fma2(K3, S2[i], v);
            v = fma2(K2, S1[i], v);
            v = fma2(K0, X1[i], v);
            ACC[i] = fma2(BT, abs2(v), ACC[i]);
        }
    }

    float xs[8];
    #pragma unroll
    for (int i = 0; i < 4; i++) {
        u64t v = fma2(pg[0], X1[i], pg[5]);
        v = fma2(pg[1], MF[i], v);
        v = fma2(pg[2], S1[i], v);
        v = fma2(pg[3], S2[i], v);
        v = fma2(pg[4], CS[i], v);
        v = add2(v, ACC[i]);
        unpack2(xs[2 * i], xs[2 * i + 1], v);
    }

    #pragma unroll
    for (int e = 0; e < 8; e++) {
        float v = xs[e];
        int k = 0;
        if (skn[63] < v) k = 64;
        if (skn[k + 31] < v) k += 32;
        if (skn[k + 15] < v) k += 16;
        if (skn[k + 7] < v) k += 8;
        if (skn[k + 3] < v) k += 4;
        if (skn[k + 1] < v) k += 2;
        if (skn[k] < v) k += 1;
        out[base + e * 256] = fmaf(ssl[k], v, sit[k]);
    }
}

// ---------------------------------------------------------------------------
extern "C" void kernel_launch(void* const* d_in, const int* in_sizes, int n_in,
                              void* d_out, int out_size) {
    const float* x     = (const float*)d_in[0];
    const int*   mask  = (const int*)  d_in[1];
    const float* b_fs  = (const float*)d_in[3];
    const float* W_in  = (const float*)d_in[4];
    const float* b_in  = (const float*)d_in[5];
    const float* adj   = (const float*)d_in[6];
    const float* W_gc  = (const float*)d_in[7];
    const float* b_gc  = (const float*)d_in[8];
    const float* W_lo  = (const float*)d_in[9];
    const float* b_lo  = (const float*)d_in[10];
    const float* pre_a = (const float*)d_in[11];
    const float* W_ro  = (const float*)d_in[12];
    const float* b_ro  = (const float*)d_in[13];
    const float* W_o1  = (const float*)d_in[14];
    const float* b_o1  = (const float*)d_in[15];
    const float* W_o2  = (const float*)d_in[16];
    const float* b_o2  = (const float*)d_in[17];
    float* out = (float*)d_out;

    cudaFuncSetAttribute(gemm_mma_kernel,
                         cudaFuncAttributeMaxDynamicSharedMemorySize,
                         GEMM_SMEM);

    coeff_kernel<<<1, 128>>>(W_in, b_in, W_gc, b_gc, W_lo, b_lo,
                             pre_a, W_ro, b_ro, W_o1, b_o1, W_o2, b_o2);
    prep_kernel<<<1024, 256>>>(adj, x, mask, b_fs);
    colsum_kernel<<<128, 256>>>(adj);
    {
        dim3 grid(16, 8, 2);
        gemm_mma_kernel<<<grid, 256, GEMM_SMEM>>>();
    }
    final_kernel<<<256, 256>>>(x, mask, b_fs, out);
}

// round 11
// speedup vs baseline: 1.2314x; 1.2314x over previous
#include <cuda_runtime.h>
#include <cuda_fp16.h>
#include <cstdint>

#define Bdim 8
#define Ndim 1024
#define Tdim 64
#define TOTAL (Bdim*Ndim*Tdim)

typedef unsigned long long u64t;

// scratch (static device memory)
__device__ float g_S[Ndim * 1024];    // K-split half 0
__device__ float g_S2[Ndim * 1024];   // K-split half 1
__device__ float g_cs[Ndim];
__device__ float g_C[6 * 64];
__device__ float g_beta[64];
__device__ float g_gamma[6];
__device__ float g_knots[127];
__device__ float g_slope[65];
__device__ float g_inter[65];
// fp16 operands: [k][col] row-major, 1024 cols (pairs packed in u32)
__device__ __align__(16) uint32_t g_Ah[1024 * 512];
__device__ __align__(16) uint32_t g_Bh[1024 * 512];

// ------------------------------ helpers -----------------------------------
__device__ __forceinline__ uint32_t smem_u32(const void* p) {
    uint32_t a;
    asm("{ .reg .u64 t; cvta.to.shared.u64 t, %1; cvt.u32.u64 %0, t; }"
        : "=r"(a) : "l"(p));
    return a;
}
__device__ __forceinline__ uint32_t pack_f16x2(float lo, float hi) {
    __half2 h = __floats2half2_rn(lo, hi);
    return *(uint32_t*)&h;
}
__device__ __forceinline__ void ldsm_x4_t(uint32_t& r0, uint32_t& r1,
                                          uint32_t& r2, uint32_t& r3,
                                          uint32_t addr) {
    asm volatile("ldmatrix.sync.aligned.m8n8.x4.trans.shared.b16 "
                 "{%0,%1,%2,%3}, [%4];"
                 : "=r"(r0), "=r"(r1), "=r"(r2), "=r"(r3) : "r"(addr));
}
__device__ __forceinline__ void mma16816(float* c, const uint32_t* a,
                                         const uint32_t* b) {
    asm volatile(
        "mma.sync.aligned.m16n8k16.row.col.f32.f16.f16.f32 "
        "{%0,%1,%2,%3}, {%4,%5,%6,%7}, {%8,%9}, {%0,%1,%2,%3};"
        : "+f"(c[0]), "+f"(c[1]), "+f"(c[2]), "+f"(c[3])
        : "r"(a[0]), "r"(a[1]), "r"(a[2]), "r"(a[3]), "r"(b[0]), "r"(b[1]));
}
__device__ __forceinline__ void cp16(uint32_t dst, const void* src) {
    asm volatile("cp.async.cg.shared.global [%0], [%1], 16;"
                 :: "r"(dst), "l"(src) : "memory");
}
// packed f32x2 ops (Blackwell base ISA)
__device__ __forceinline__ u64t fma2(u64t a, u64t b, u64t c) {
    u64t d;
    asm("fma.rn.f32x2 %0, %1, %2, %3;" : "=l"(d) : "l"(a), "l"(b), "l"(c));
    return d;
}
__device__ __forceinline__ u64t add2(u64t a, u64t b) {
    u64t d;
    asm("add.rn.f32x2 %0, %1, %2;" : "=l"(d) : "l"(a), "l"(b));
    return d;
}
__device__ __forceinline__ u64t abs2(u64t a) {
    u64t d;
    asm("and.b64 %0, %1, 0x7FFFFFFF7FFFFFFF;" : "=l"(d) : "l"(a));
    return d;
}
__device__ __forceinline__ u64t pack2(float lo, float hi) {
    u64t d;
    asm("mov.b64 %0, {%1, %2};" : "=l"(d) : "f"(lo), "f"(hi));
    return d;
}
__device__ __forceinline__ void unpack2(float& lo, float& hi, u64t v) {
    asm("mov.b64 {%0, %1}, %2;" : "=f"(lo), "=f"(hi) : "l"(v));
}

// ---------------------------------------------------------------------------
// Kernel 1: coefficient folding + PW-linear MLP tables + zero g_cs.
// ---------------------------------------------------------------------------
__global__ void coeff_kernel(const float* __restrict__ W_in,
                             const float* __restrict__ b_in,
                             const float* __restrict__ W_gc,
                             const float* __restrict__ b_gc,
                             const float* __restrict__ W_lo,
                             const float* __restrict__ b_lo,
                             const float* __restrict__ prelu_a,
                             const float* __restrict__ W_ro,
                             const float* __restrict__ b_ro,
                             const float* __restrict__ W_o1,
                             const float* __restrict__ b_o1,
                             const float* __restrict__ W_o2,
                             const float* __restrict__ b_o2) {
    __shared__ float w0[64], w1[64], bi[64];
    __shared__ float A[6][64];
    __shared__ float sC[6][64];
    __shared__ float sAl[64];
    __shared__ float kno[64], srt[64];
    __shared__ int   srank[64];
    __shared__ float sw1[64], sb1[64], sw2[64];
    int t = threadIdx.x;

    if (t < 64) {
        w0[t] = W_in[t * 66 + 0];
        w1[t] = W_in[t * 66 + 1];
        bi[t] = b_in[t];
    }
    __syncthreads();
    if (t < 64) {
        float a0 = 0.f, a1 = 0.f, a2 = 0.f, a3 = 0.f, a4 = 0.f, a5 = 0.f;
        for (int k = 0; k < 64; k++) {
            float g1 = W_gc[t * 128 + k];
            float g2 = W_gc[t * 128 + 64 + k];
            a0 = fmaf(g1, w0[k], a0); a1 = fmaf(g1, w1[k], a1);
            a5 = fmaf(g1, bi[k], a5);
            a2 = fmaf(g2, w0[k], a2); a3 = fmaf(g2, w1[k], a3);
            a4 = fmaf(g2, bi[k], a4);
        }
        A[0][t] = a0; A[1][t] = a1; A[2][t] = a2;
        A[3][t] = a3; A[4][t] = a4; A[5][t] = a5 + b_gc[t];
    }
    __syncthreads();
    if (t < 64) {
        float c[6] = {0.f, 0.f, 0.f, 0.f, 0.f, 0.f};
        for (int k = 0; k < 64; k++) {
            float wl = W_lo[t * 128 + k];
            #pragma unroll
            for (int i = 0; i < 6; i++) c[i] = fmaf(wl, A[i][k], c[i]);
        }
        c[5] += b_lo[t];
        #pragma unroll
        for (int i = 0; i < 6; i++) { sC[i][t] = c[i]; g_C[i * 64 + t] = c[i]; }
        float a = prelu_a[0];
        float wr = W_ro[t];
        sAl[t] = wr * 0.5f * (1.f + a);
        g_beta[t] = wr * 0.5f * (1.f - a);
        sw1[t] = W_o1[t]; sb1[t] = b_o1[t]; sw2[t] = W_o2[t];
    }
    __syncthreads();
    if (t < 6) {
        float g = 0.f;
        for (int k = 0; k < 64; k++) g = fmaf(sAl[k], sC[t][k], g);
        if (t == 5) g += b_ro[0];
        g_gamma[t] = g;
    }
    if (t < 64) {
        float w = sw1[t];
        kno[t] = (w != 0.f) ? (-sb1[t] / w) : 3.0e38f;
    }
    __syncthreads();
    if (t < 64) {
        float kt = kno[t];
        int r = 0;
        for (int j = 0; j < 64; j++)
            r += (kno[j] < kt) || (kno[j] == kt && j < t);
        srank[t] = r;
        srt[r] = kt;
    }
    __syncthreads();
    if (t < 64) g_knots[t] = srt[t];
    for (int i = 64 + t; i < 127; i += blockDim.x) g_knots[i] = 3.2e38f;
    if (t < 65) {
        float sl = 0.f, in = b_o2[0];
        for (int f = 0; f < 64; f++) {
            float w = sw1[f], w2 = sw2[f];
            if (w > 0.f) {
                if (srank[f] < t) { sl = fmaf(w2, w, sl); in = fmaf(w2, sb1[f], in); }
            } else if (w < 0.f) {
                if (srank[f] >= t) { sl = fmaf(w2, w, sl); in = fmaf(w2, sb1[f], in); }
            } else {
                in = fmaf(w2, fmaxf(sb1[f], 0.f), in);
            }
        }
        g_slope[t] = sl; g_inter[t] = in;
    }
    for (int i = t; i < Ndim; i += blockDim.x) g_cs[i] = 0.f;
}

// ---------------------------------------------------------------------------
// Kernel 2: convert adj and R=(x1|mask) to fp16. grid 1024 x 256.
// ---------------------------------------------------------------------------
__global__ void prep_kernel(const float* __restrict__ adj,
                            const float* __restrict__ x,
                            const int*   __restrict__ mask,
                            const float* __restrict__ b_fs) {
    const int k = blockIdx.x;
    const int t = threadIdx.x;
    const float bfs0 = b_fs[0];

    float4 a = *(const float4*)(adj + k * 1024 + t * 4);
    uint2 hp;
    hp.x = pack_f16x2(a.x, a.y);
    hp.y = pack_f16x2(a.z, a.w);
    *(uint2*)&g_Ah[k * 512 + t * 2] = hp;

    int j = 2 * t;
    int b = j >> 6, tt = j & 63;
    int gi = b * 65536 + k * 64 + tt;
    int m0 = mask[gi], m1 = mask[gi + 1];
    float v0 = m0 ? x[gi] : bfs0;
    float v1 = m1 ? x[gi + 1] : bfs0;
    g_Bh[k * 512 + t] = pack_f16x2(v0, v1);
    g_Bh[k * 512 + 256 + t] = pack_f16x2((float)m0, (float)m1);
}

// ---------------------------------------------------------------------------
// Kernel 3: column sums of adj. 128 blocks x 256.
// ---------------------------------------------------------------------------
__global__ void colsum_kernel(const float* __restrict__ adj) {
    int m = (blockIdx.x & 3) * 256 + threadIdx.x;
    int n0 = (blockIdx.x >> 2) * 32;
    float s = 0.f;
    #pragma unroll 8
    for (int n = n0; n < n0 + 32; n++)
        s += adj[n * Ndim + m];
    atomicAdd(&g_cs[m], s);
}

// ---------------------------------------------------------------------------
// Kernel 4: fp16 single-product GEMM, 4-stage cp.async, one sync/iter.
//   CTA: D[128 m, 64 j] over K=512; K-chunk 64, 8 iterations.
//   grid (16 j, 8 m, 2 ksplit) = 256 CTAs, 256 threads, 2 CTAs/SM.
// ---------------------------------------------------------------------------
#define A_STRIDE_B 272
#define B_STRIDE_B 144
#define ST_AH 0
#define ST_BH 17408
#define STAGE_STRIDE 26624
#define NSTAGE 4
#define GEMM_SMEM (NSTAGE * STAGE_STRIDE)   // 106496

__global__ void __launch_bounds__(256, 2)
gemm_mma_kernel() {
    extern __shared__ __align__(16) char smp[];
    const uint32_t sb = smem_u32(smp);

    const int tid  = threadIdx.x;
    const int lane = tid & 31;
    const int wid  = tid >> 5;
    const int warp_m = (wid & 3) * 32;
    const int warp_j = (wid >> 2) * 32;
    const int mcta = blockIdx.y * 128;
    const int bx   = blockIdx.x;
    const int j0   = bx * 64;
    const int kbase = blockIdx.z * 512;

    // ldmatrix per-lane addresses (validated fragment mapping)
    const int aK = (lane & 7) + ((lane & 16) ? 8 : 0);
    const int aM = (lane & 8) ? 8 : 0;
    const int bK = (lane & 7) + ((lane & 8) ? 8 : 0);
    const int bJ = (lane & 16) ? 8 : 0;
    const uint32_t aBase = sb + ST_AH + (uint32_t)(aK * A_STRIDE_B + (warp_m + aM) * 2);
    const uint32_t bBase = sb + ST_BH + (uint32_t)(bK * B_STRIDE_B + (warp_j + bJ) * 2);

    float acc[2][4][4];
    #pragma unroll
    for (int mt = 0; mt < 2; mt++)
        #pragma unroll
        for (int nt = 0; nt < 4; nt++)
            #pragma unroll
            for (int r = 0; r < 4; r++) acc[mt][nt][r] = 0.f;

    // cp.async geometry (K-chunk 64):
    //  A: 64 rows x 16 slots -> 4/thread; B: 64 rows x 8 slots -> 2/thread
    const int arow = tid >> 4, acol = tid & 15;
    const int brow = tid >> 3, bcol = tid & 7;

    auto issue_chunk = [&](int it) {
        const int s = it & (NSTAGE - 1);
        const int k0 = kbase + it * 64;
        const uint32_t stg = sb + s * STAGE_STRIDE;
        #pragma unroll
        for (int i = 0; i < 4; i++) {
            int row = arow + i * 16;
            uint32_t doff = row * A_STRIDE_B + acol * 16;
            size_t goff = (size_t)(k0 + row) * 2048 + mcta * 2 + acol * 16;
            cp16(stg + ST_AH + doff, (const char*)g_Ah + goff);
        }
        #pragma unroll
        for (int i = 0; i < 2; i++) {
            int row = brow + i * 32;
            uint32_t doff = row * B_STRIDE_B + bcol * 16;
            size_t goff = (size_t)(k0 + row) * 2048 + j0 * 2 + bcol * 16;
            cp16(stg + ST_BH + doff, (const char*)g_Bh + goff);
        }
        asm volatile("cp.async.commit_group;" ::: "memory");
    };

    auto compute = [&](int s) {
        const uint32_t aS = aBase + s * STAGE_STRIDE;
        const uint32_t bS = bBase + s * STAGE_STRIDE;
        #pragma unroll
        for (int ks = 0; ks < 4; ks++) {
            uint32_t aKaddr = aS + ks * (16 * A_STRIDE_B);
            uint32_t bKaddr = bS + ks * (16 * B_STRIDE_B);
            uint32_t ah[2][4], bh[2][4];
            ldsm_x4_t(ah[0][0], ah[0][1], ah[0][2], ah[0][3], aKaddr);
            ldsm_x4_t(ah[1][0], ah[1][1], ah[1][2], ah[1][3], aKaddr + 32);
            ldsm_x4_t(bh[0][0], bh[0][1], bh[0][2], bh[0][3], bKaddr);
            ldsm_x4_t(bh[1][0], bh[1][1], bh[1][2], bh[1][3], bKaddr + 32);
            #pragma unroll
            for (int mt = 0; mt < 2; mt++)
                #pragma unroll
                for (int nt = 0; nt < 4; nt++) {
                    const uint32_t* Bh = &bh[nt >> 1][(nt & 1) * 2];
                    mma16816(acc[mt][nt], ah[mt], Bh);
                }
        }
    };

    issue_chunk(0);
    issue_chunk(1);
    issue_chunk(2);
    for (int it = 0; it < 8; ++it) {
        if (it < 6)      asm volatile("cp.async.wait_group 2;" ::: "memory");
        else if (it == 6) asm volatile("cp.async.wait_group 1;" ::: "memory");
        else              asm volatile("cp.async.wait_group 0;" ::: "memory");
        __syncthreads();
        if (it < 5) issue_chunk(it + 3);
        compute(it & (NSTAGE - 1));
    }

    // epilogue
    float* dstbuf = blockIdx.z ? g_S2 : g_S;
    const int gid = lane >> 2, tig = lane & 3;
    const int jw = j0 + warp_j + 2 * tig;
    #pragma unroll
    for (int mt = 0; mt < 2; mt++) {
        int m = mcta + warp_m + mt * 16 + gid;
        #pragma unroll
        for (int nt = 0; nt < 4; nt++) {
            int j = jw + nt * 8;
            *(float2*)&dstbuf[m * 1024 + j] =
                make_float2(acc[mt][nt][0], acc[mt][nt][1]);
            *(float2*)&dstbuf[(m + 8) * 1024 + j] =
                make_float2(acc[mt][nt][2], acc[mt][nt][3]);
        }
    }
}

// ---------------------------------------------------------------------------
// Kernel 5: per-element tail, packed f32x2, E=4. 512 blocks x 256.
// ---------------------------------------------------------------------------
__global__ void __launch_bounds__(256)
final_kernel(const float* __restrict__ x,
             const int*   __restrict__ mask,
             const float* __restrict__ b_fs,
             float* __restrict__ out) {
    __shared__ u64t pc0[64], pc1[64], pc2[64], pc3[64], pc4[64], pc5[64], pbt[64];
    __shared__ float skn[127], ssl[65], sit[65];
    __shared__ u64t pg[6];
    int t = threadIdx.x;
    if (t < 64) {
        float c;
        c = g_C[t];       pc0[t] = pack2(c, c);
        c = g_C[64 + t];  pc1[t] = pack2(c, c);
        c = g_C[128 + t]; pc2[t] = pack2(c, c);
        c = g_C[192 + t]; pc3[t] = pack2(c, c);
        c = g_C[256 + t]; pc4[t] = pack2(c, c);
        c = g_C[320 + t]; pc5[t] = pack2(c, c);
        c = g_beta[t];    pbt[t] = pack2(c, c);
    }
    if (t < 127) skn[t] = g_knots[t];
    if (t < 65) { ssl[t] = g_slope[t]; sit[t] = g_inter[t]; }
    if (t < 6) { float g = g_gamma[t]; pg[t] = pack2(g, g); }
    __syncthreads();

    const float bfs0 = b_fs[0];
    const int base = blockIdx.x * 1024 + t;

    float x1[4], mf[4], s1[4], s2[4], csv[4];
    #pragma unroll
    for (int e = 0; e < 4; e++) {
        int idx = base + e * 256;
        int mi = mask[idx];
        float xv = x[idx];
        mf[e] = (float)mi;
        x1[e] = mi ? xv : bfs0;
        int n = (idx >> 6) & (Ndim - 1);
        int b = idx >> 16;
        int tt = idx & 63;
        int j = (b << 6) | tt;
        s1[e] = g_S[n * 1024 + j] + g_S2[n * 1024 + j];
        s2[e] = g_S[n * 1024 + 512 + j] + g_S2[n * 1024 + 512 + j];
        csv[e] = g_cs[n];
    }

    u64t X1a = pack2(x1[0], x1[1]), X1b = pack2(x1[2], x1[3]);
    u64t MFa = pack2(mf[0], mf[1]), MFb = pack2(mf[2], mf[3]);
    u64t S1a = pack2(s1[0], s1[1]), S1b = pack2(s1[2], s1[3]);
    u64t S2a = pack2(s2[0], s2[1]), S2b = pack2(s2[2], s2[3]);
    u64t CSa = pack2(csv[0], csv[1]), CSb = pack2(csv[2], csv[3]);
    u64t ACCa = 0ull, ACCb = 0ull;

    #pragma unroll
    for (int o = 0; o < 64; o++) {
        u64t K0 = pc0[o], K1 = pc1[o], K2 = pc2[o], K3 = pc3[o];
        u64t K4 = pc4[o], K5 = pc5[o], BT = pbt[o];
        u64t va = fma2(K4, CSa, K5);
        va = fma2(K1, MFa, va);
        va = fma2(K3, S2a, va);
        va = fma2(K2, S1a, va);
        va = fma2(K0, X1a, va);
        ACCa = fma2(BT, abs2(va), ACCa);
        u64t vb = fma2(K4, CSb, K5);
        vb = fma2(K1, MFb, vb);
        vb = fma2(K3, S2b, vb);
        vb = fma2(K2, S1b, vb);
        vb = fma2(K0, X1b, vb);
        ACCb = fma2(BT, abs2(vb), ACCb);
    }

    u64t xsA = fma2(pg[0], X1a, pg[5]);
    xsA = fma2(pg[1], MFa, xsA);
    xsA = fma2(pg[2], S1a, xsA);
    xsA = fma2(pg[3], S2a, xsA);
    xsA = fma2(pg[4], CSa, xsA);
    xsA = add2(xsA, ACCa);
    u64t xsB = fma2(pg[0], X1b, pg[5]);
    xsB = fma2(pg[1], MFb, xsB);
    xsB = fma2(pg[2], S1b, xsB);
    xsB = fma2(pg[3], S2b, xsB);
    xsB = fma2(pg[4], CSb, xsB);
    xsB = add2(xsB, ACCb);

    float xs[4];
    unpack2(xs[0], xs[1], xsA);
    unpack2(xs[2], xs[3], xsB);

    #pragma unroll
    for (int e = 0; e < 4; e++) {
        float v = xs[e];
        int k = 0;
        if (skn[63] < v) k = 64;
        if (skn[k + 31] < v) k += 32;
        if (skn[k + 15] < v) k += 16;
        if (skn[k + 7] < v) k += 8;
        if (skn[k + 3] < v) k += 4;
        if (skn[k + 1] < v) k += 2;
        if (skn[k] < v) k += 1;
        out[base + e * 256] = fmaf(ssl[k], v, sit[k]);
    }
}

// ---------------------------------------------------------------------------
extern "C" void kernel_launch(void* const* d_in, const int* in_sizes, int n_in,
                              void* d_out, int out_size) {
    const float* x     = (const float*)d_in[0];
    const int*   mask  = (const int*)  d_in[1];
    const float* b_fs  = (const float*)d_in[3];
    const float* W_in  = (const float*)d_in[4];
    const float* b_in  = (const float*)d_in[5];
    const float* adj   = (const float*)d_in[6];
    const float* W_gc  = (const float*)d_in[7];
    const float* b_gc  = (const float*)d_in[8];
    const float* W_lo  = (const float*)d_in[9];
    const float* b_lo  = (const float*)d_in[10];
    const float* pre_a = (const float*)d_in[11];
    const float* W_ro  = (const float*)d_in[12];
    const float* b_ro  = (const float*)d_in[13];
    const float* W_o1  = (const float*)d_in[14];
    const float* b_o1  = (const float*)d_in[15];
    const float* W_o2  = (const float*)d_in[16];
    const float* b_o2  = (const float*)d_in[17];
    float* out = (float*)d_out;

    cudaFuncSetAttribute(gemm_mma_kernel,
                         cudaFuncAttributeMaxDynamicSharedMemorySize,
                         GEMM_SMEM);

    coeff_kernel<<<1, 128>>>(W_in, b_in, W_gc, b_gc, W_lo, b_lo,
                             pre_a, W_ro, b_ro, W_o1, b_o1, W_o2, b_o2);
    prep_kernel<<<1024, 256>>>(adj, x, mask, b_fs);
    colsum_kernel<<<128, 256>>>(adj);
    {
        dim3 grid(16, 8, 2);
        gemm_mma_kernel<<<grid, 256, GEMM_SMEM>>>();
    }
    final_kernel<<<512, 256>>>(x, mask, b_fs, out);
}

// round 12
// speedup vs baseline: 1.3001x; 1.0558x over previous
#include <cuda_runtime.h>
#include <cuda_fp16.h>
#include <cstdint>

#define Bdim 8
#define Ndim 1024
#define Tdim 64
#define TOTAL (Bdim*Ndim*Tdim)

typedef unsigned long long u64t;

// scratch (static device memory)
__device__ float g_S[Ndim * 1024];    // K-split half 0
__device__ float g_S2[Ndim * 1024];   // K-split half 1
__device__ float g_cs[Ndim];
__device__ float g_C[6 * 64];
__device__ float g_beta[64];
__device__ float g_gamma[6];
__device__ float g_knots[127];
__device__ float g_slope[65];
__device__ float g_inter[65];
// fp16 operands: [k][col] row-major, 1024 cols (pairs packed in u32)
__device__ __align__(16) uint32_t g_Ah[1024 * 512];
__device__ __align__(16) uint32_t g_Bh[1024 * 512];

// ------------------------------ helpers -----------------------------------
__device__ __forceinline__ uint32_t smem_u32(const void* p) {
    uint32_t a;
    asm("{ .reg .u64 t; cvta.to.shared.u64 t, %1; cvt.u32.u64 %0, t; }"
        : "=r"(a) : "l"(p));
    return a;
}
__device__ __forceinline__ uint32_t pack_f16x2(float lo, float hi) {
    __half2 h = __floats2half2_rn(lo, hi);
    return *(uint32_t*)&h;
}
__device__ __forceinline__ void ldsm_x4_t(uint32_t& r0, uint32_t& r1,
                                          uint32_t& r2, uint32_t& r3,
                                          uint32_t addr) {
    asm volatile("ldmatrix.sync.aligned.m8n8.x4.trans.shared.b16 "
                 "{%0,%1,%2,%3}, [%4];"
                 : "=r"(r0), "=r"(r1), "=r"(r2), "=r"(r3) : "r"(addr));
}
__device__ __forceinline__ void mma16816(float* c, const uint32_t* a,
                                         const uint32_t* b) {
    asm volatile(
        "mma.sync.aligned.m16n8k16.row.col.f32.f16.f16.f32 "
        "{%0,%1,%2,%3}, {%4,%5,%6,%7}, {%8,%9}, {%0,%1,%2,%3};"
        : "+f"(c[0]), "+f"(c[1]), "+f"(c[2]), "+f"(c[3])
        : "r"(a[0]), "r"(a[1]), "r"(a[2]), "r"(a[3]), "r"(b[0]), "r"(b[1]));
}
__device__ __forceinline__ void cp16(uint32_t dst, const void* src) {
    asm volatile("cp.async.cg.shared.global [%0], [%1], 16;"
                 :: "r"(dst), "l"(src) : "memory");
}
// packed f32x2 ops (Blackwell base ISA)
__device__ __forceinline__ u64t fma2(u64t a, u64t b, u64t c) {
    u64t d;
    asm("fma.rn.f32x2 %0, %1, %2, %3;" : "=l"(d) : "l"(a), "l"(b), "l"(c));
    return d;
}
__device__ __forceinline__ u64t add2(u64t a, u64t b) {
    u64t d;
    asm("add.rn.f32x2 %0, %1, %2;" : "=l"(d) : "l"(a), "l"(b));
    return d;
}
__device__ __forceinline__ u64t abs2(u64t a) {
    u64t d;
    asm("and.b64 %0, %1, 0x7FFFFFFF7FFFFFFF;" : "=l"(d) : "l"(a));
    return d;
}
__device__ __forceinline__ u64t pack2(float lo, float hi) {
    u64t d;
    asm("mov.b64 %0, {%1, %2};" : "=l"(d) : "f"(lo), "f"(hi));
    return d;
}
__device__ __forceinline__ void unpack2(float& lo, float& hi, u64t v) {
    asm("mov.b64 {%0, %1}, %2;" : "=f"(lo), "=f"(hi) : "l"(v));
}

// ---------------------------------------------------------------------------
// Kernel 1 (merged setup): grid 1153 x 256.
//   block 0        : coefficient folding + PW-linear tables
//   blocks 1..128  : colsum partial atomics (g_cs pre-zeroed by memset)
//   blocks 129..   : prep (fp16 conversion of adj and R)
// ---------------------------------------------------------------------------
__global__ void __launch_bounds__(256)
setup_kernel(const float* __restrict__ adj,
             const float* __restrict__ x,
             const int*   __restrict__ mask,
             const float* __restrict__ b_fs,
             const float* __restrict__ W_in,
             const float* __restrict__ b_in,
             const float* __restrict__ W_gc,
             const float* __restrict__ b_gc,
             const float* __restrict__ W_lo,
             const float* __restrict__ b_lo,
             const float* __restrict__ prelu_a,
             const float* __restrict__ W_ro,
             const float* __restrict__ b_ro,
             const float* __restrict__ W_o1,
             const float* __restrict__ b_o1,
             const float* __restrict__ W_o2,
             const float* __restrict__ b_o2) {
    __shared__ float w0[64], w1[64], bi[64];
    __shared__ float A[6][64];
    __shared__ float sC[6][64];
    __shared__ float sAl[64];
    __shared__ float kno[64], srt[64];
    __shared__ int   srank[64];
    __shared__ float sw1[64], sb1[64], sw2[64];

    const int blk = blockIdx.x;
    const int t = threadIdx.x;

    if (blk == 0) {
        // ---------------- coeff ----------------
        if (t < 64) {
            w0[t] = W_in[t * 66 + 0];
            w1[t] = W_in[t * 66 + 1];
            bi[t] = b_in[t];
        }
        __syncthreads();
        if (t < 64) {
            float a0 = 0.f, a1 = 0.f, a2 = 0.f, a3 = 0.f, a4 = 0.f, a5 = 0.f;
            for (int k = 0; k < 64; k++) {
                float g1 = W_gc[t * 128 + k];
                float g2 = W_gc[t * 128 + 64 + k];
                a0 = fmaf(g1, w0[k], a0); a1 = fmaf(g1, w1[k], a1);
                a5 = fmaf(g1, bi[k], a5);
                a2 = fmaf(g2, w0[k], a2); a3 = fmaf(g2, w1[k], a3);
                a4 = fmaf(g2, bi[k], a4);
            }
            A[0][t] = a0; A[1][t] = a1; A[2][t] = a2;
            A[3][t] = a3; A[4][t] = a4; A[5][t] = a5 + b_gc[t];
        }
        __syncthreads();
        if (t < 64) {
            float c[6] = {0.f, 0.f, 0.f, 0.f, 0.f, 0.f};
            for (int k = 0; k < 64; k++) {
                float wl = W_lo[t * 128 + k];
                #pragma unroll
                for (int i = 0; i < 6; i++) c[i] = fmaf(wl, A[i][k], c[i]);
            }
            c[5] += b_lo[t];
            #pragma unroll
            for (int i = 0; i < 6; i++) { sC[i][t] = c[i]; g_C[i * 64 + t] = c[i]; }
            float a = prelu_a[0];
            float wr = W_ro[t];
            sAl[t] = wr * 0.5f * (1.f + a);
            g_beta[t] = wr * 0.5f * (1.f - a);
            sw1[t] = W_o1[t]; sb1[t] = b_o1[t]; sw2[t] = W_o2[t];
        }
        __syncthreads();
        if (t < 6) {
            float g = 0.f;
            for (int k = 0; k < 64; k++) g = fmaf(sAl[k], sC[t][k], g);
            if (t == 5) g += b_ro[0];
            g_gamma[t] = g;
        }
        if (t < 64) {
            float w = sw1[t];
            kno[t] = (w != 0.f) ? (-sb1[t] / w) : 3.0e38f;
        }
        __syncthreads();
        if (t < 64) {
            float kt = kno[t];
            int r = 0;
            for (int j = 0; j < 64; j++)
                r += (kno[j] < kt) || (kno[j] == kt && j < t);
            srank[t] = r;
            srt[r] = kt;
        }
        __syncthreads();
        if (t < 64) g_knots[t] = srt[t];
        for (int i = 64 + t; i < 127; i += blockDim.x) g_knots[i] = 3.2e38f;
        if (t < 65) {
            float sl = 0.f, in = b_o2[0];
            for (int f = 0; f < 64; f++) {
                float w = sw1[f], w2 = sw2[f];
                if (w > 0.f) {
                    if (srank[f] < t) { sl = fmaf(w2, w, sl); in = fmaf(w2, sb1[f], in); }
                } else if (w < 0.f) {
                    if (srank[f] >= t) { sl = fmaf(w2, w, sl); in = fmaf(w2, sb1[f], in); }
                } else {
                    in = fmaf(w2, fmaxf(sb1[f], 0.f), in);
                }
            }
            g_slope[t] = sl; g_inter[t] = in;
        }
    } else if (blk <= 128) {
        // ---------------- colsum partial ----------------
        int bb = blk - 1;
        int m = (bb & 3) * 256 + t;
        int n0 = (bb >> 2) * 32;
        float s = 0.f;
        #pragma unroll 8
        for (int n = n0; n < n0 + 32; n++)
            s += adj[n * Ndim + m];
        atomicAdd(&g_cs[m], s);
    } else {
        // ---------------- prep ----------------
        const int k = blk - 129;
        const float bfs0 = b_fs[0];

        float4 a = *(const float4*)(adj + k * 1024 + t * 4);
        uint2 hp;
        hp.x = pack_f16x2(a.x, a.y);
        hp.y = pack_f16x2(a.z, a.w);
        *(uint2*)&g_Ah[k * 512 + t * 2] = hp;

        int j = 2 * t;
        int b = j >> 6, tt = j & 63;
        int gi = b * 65536 + k * 64 + tt;
        int m0 = mask[gi], m1 = mask[gi + 1];
        float v0 = m0 ? x[gi] : bfs0;
        float v1 = m1 ? x[gi + 1] : bfs0;
        g_Bh[k * 512 + t] = pack_f16x2(v0, v1);
        g_Bh[k * 512 + 256 + t] = pack_f16x2((float)m0, (float)m1);
    }
}

// ---------------------------------------------------------------------------
// Kernel 2: fp16 single-product GEMM, 4-stage cp.async, one sync/iter.
//   CTA: D[128 m, 64 j] over K=512; K-chunk 64, 8 iterations.
//   grid (16 j, 8 m, 2 ksplit) = 256 CTAs, 256 threads, 2 CTAs/SM.
// ---------------------------------------------------------------------------
#define A_STRIDE_B 272
#define B_STRIDE_B 144
#define ST_AH 0
#define ST_BH 17408
#define STAGE_STRIDE 26624
#define NSTAGE 4
#define GEMM_SMEM (NSTAGE * STAGE_STRIDE)   // 106496

__global__ void __launch_bounds__(256, 2)
gemm_mma_kernel() {
    extern __shared__ __align__(16) char smp[];
    const uint32_t sb = smem_u32(smp);

    const int tid  = threadIdx.x;
    const int lane = tid & 31;
    const int wid  = tid >> 5;
    const int warp_m = (wid & 3) * 32;
    const int warp_j = (wid >> 2) * 32;
    const int mcta = blockIdx.y * 128;
    const int bx   = blockIdx.x;
    const int j0   = bx * 64;
    const int kbase = blockIdx.z * 512;

    // ldmatrix per-lane addresses (validated fragment mapping)
    const int aK = (lane & 7) + ((lane & 16) ? 8 : 0);
    const int aM = (lane & 8) ? 8 : 0;
    const int bK = (lane & 7) + ((lane & 8) ? 8 : 0);
    const int bJ = (lane & 16) ? 8 : 0;
    const uint32_t aBase = sb + ST_AH + (uint32_t)(aK * A_STRIDE_B + (warp_m + aM) * 2);
    const uint32_t bBase = sb + ST_BH + (uint32_t)(bK * B_STRIDE_B + (warp_j + bJ) * 2);

    float acc[2][4][4];
    #pragma unroll
    for (int mt = 0; mt < 2; mt++)
        #pragma unroll
        for (int nt = 0; nt < 4; nt++)
            #pragma unroll
            for (int r = 0; r < 4; r++) acc[mt][nt][r] = 0.f;

    // cp.async geometry (K-chunk 64):
    //  A: 64 rows x 16 slots -> 4/thread; B: 64 rows x 8 slots -> 2/thread
    const int arow = tid >> 4, acol = tid & 15;
    const int brow = tid >> 3, bcol = tid & 7;

    auto issue_chunk = [&](int it) {
        const int s = it & (NSTAGE - 1);
        const int k0 = kbase + it * 64;
        const uint32_t stg = sb + s * STAGE_STRIDE;
        #pragma unroll
        for (int i = 0; i < 4; i++) {
            int row = arow + i * 16;
            uint32_t doff = row * A_STRIDE_B + acol * 16;
            size_t goff = (size_t)(k0 + row) * 2048 + mcta * 2 + acol * 16;
            cp16(stg + ST_AH + doff, (const char*)g_Ah + goff);
        }
        #pragma unroll
        for (int i = 0; i < 2; i++) {
            int row = brow + i * 32;
            uint32_t doff = row * B_STRIDE_B + bcol * 16;
            size_t goff = (size_t)(k0 + row) * 2048 + j0 * 2 + bcol * 16;
            cp16(stg + ST_BH + doff, (const char*)g_Bh + goff);
        }
        asm volatile("cp.async.commit_group;" ::: "memory");
    };

    auto compute = [&](int s) {
        const uint32_t aS = aBase + s * STAGE_STRIDE;
        const uint32_t bS = bBase + s * STAGE_STRIDE;
        #pragma unroll
        for (int ks = 0; ks < 4; ks++) {
            uint32_t aKaddr = aS + ks * (16 * A_STRIDE_B);
            uint32_t bKaddr = bS + ks * (16 * B_STRIDE_B);
            uint32_t ah[2][4], bh[2][4];
            ldsm_x4_t(ah[0][0], ah[0][1], ah[0][2], ah[0][3], aKaddr);
            ldsm_x4_t(ah[1][0], ah[1][1], ah[1][2], ah[1][3], aKaddr + 32);
            ldsm_x4_t(bh[0][0], bh[0][1], bh[0][2], bh[0][3], bKaddr);
            ldsm_x4_t(bh[1][0], bh[1][1], bh[1][2], bh[1][3], bKaddr + 32);
            #pragma unroll
            for (int mt = 0; mt < 2; mt++)
                #pragma unroll
                for (int nt = 0; nt < 4; nt++) {
                    const uint32_t* Bh = &bh[nt >> 1][(nt & 1) * 2];
                    mma16816(acc[mt][nt], ah[mt], Bh);
                }
        }
    };

    issue_chunk(0);
    issue_chunk(1);
    issue_chunk(2);
    for (int it = 0; it < 8; ++it) {
        if (it < 6)      asm volatile("cp.async.wait_group 2;" ::: "memory");
        else if (it == 6) asm volatile("cp.async.wait_group 1;" ::: "memory");
        else              asm volatile("cp.async.wait_group 0;" ::: "memory");
        __syncthreads();
        if (it < 5) issue_chunk(it + 3);
        compute(it & (NSTAGE - 1));
    }

    // epilogue
    float* dstbuf = blockIdx.z ? g_S2 : g_S;
    const int gid = lane >> 2, tig = lane & 3;
    const int jw = j0 + warp_j + 2 * tig;
    #pragma unroll
    for (int mt = 0; mt < 2; mt++) {
        int m = mcta + warp_m + mt * 16 + gid;
        #pragma unroll
        for (int nt = 0; nt < 4; nt++) {
            int j = jw + nt * 8;
            *(float2*)&dstbuf[m * 1024 + j] =
                make_float2(acc[mt][nt][0], acc[mt][nt][1]);
            *(float2*)&dstbuf[(m + 8) * 1024 + j] =
                make_float2(acc[mt][nt][2], acc[mt][nt][3]);
        }
    }
}

// ---------------------------------------------------------------------------
// Kernel 3: per-element tail, packed f32x2, E=4, LDS.128 coeff loads.
// 512 blocks x 256.
// ---------------------------------------------------------------------------
__global__ void __launch_bounds__(256)
final_kernel(const float* __restrict__ x,
             const int*   __restrict__ mask,
             const float* __restrict__ b_fs,
             float* __restrict__ out) {
    __shared__ __align__(16) ulonglong2 pcq[64][4];
    __shared__ float skn[127], ssl[65], sit[65];
    __shared__ u64t pg[6];
    int t = threadIdx.x;
    if (t < 64) {
        float c0 = g_C[t],       c1 = g_C[64 + t],  c2 = g_C[128 + t];
        float c3 = g_C[192 + t], c4 = g_C[256 + t], c5 = g_C[320 + t];
        float bt = g_beta[t];
        pcq[t][0] = make_ulonglong2(pack2(c0, c0), pack2(c1, c1));
        pcq[t][1] = make_ulonglong2(pack2(c2, c2), pack2(c3, c3));
        pcq[t][2] = make_ulonglong2(pack2(c4, c4), pack2(c5, c5));
        pcq[t][3] = make_ulonglong2(pack2(bt, bt), 0ull);
    }
    if (t < 127) skn[t] = g_knots[t];
    if (t < 65) { ssl[t] = g_slope[t]; sit[t] = g_inter[t]; }
    if (t < 6) { float g = g_gamma[t]; pg[t] = pack2(g, g); }
    __syncthreads();

    const float bfs0 = b_fs[0];
    const int base = blockIdx.x * 1024 + t;

    float x1[4], mf[4], s1[4], s2[4], csv[4];
    #pragma unroll
    for (int e = 0; e < 4; e++) {
        int idx = base + e * 256;
        int mi = mask[idx];
        float xv = x[idx];
        mf[e] = (float)mi;
        x1[e] = mi ? xv : bfs0;
        int n = (idx >> 6) & (Ndim - 1);
        int b = idx >> 16;
        int tt = idx & 63;
        int j = (b << 6) | tt;
        s1[e] = g_S[n * 1024 + j] + g_S2[n * 1024 + j];
        s2[e] = g_S[n * 1024 + 512 + j] + g_S2[n * 1024 + 512 + j];
        csv[e] = g_cs[n];
    }

    u64t X1a = pack2(x1[0], x1[1]), X1b = pack2(x1[2], x1[3]);
    u64t MFa = pack2(mf[0], mf[1]), MFb = pack2(mf[2], mf[3]);
    u64t S1a = pack2(s1[0], s1[1]), S1b = pack2(s1[2], s1[3]);
    u64t S2a = pack2(s2[0], s2[1]), S2b = pack2(s2[2], s2[3]);
    u64t CSa = pack2(csv[0], csv[1]), CSb = pack2(csv[2], csv[3]);
    u64t ACCa = 0ull, ACCb = 0ull;

    #pragma unroll
    for (int o = 0; o < 64; o++) {
        ulonglong2 q0 = pcq[o][0];
        ulonglong2 q1 = pcq[o][1];
        ulonglong2 q2 = pcq[o][2];
        ulonglong2 q3 = pcq[o][3];
        u64t K0 = q0.x, K1 = q0.y, K2 = q1.x, K3 = q1.y;
        u64t K4 = q2.x, K5 = q2.y, BT = q3.x;
        u64t va = fma2(K4, CSa, K5);
        va = fma2(K1, MFa, va);
        va = fma2(K3, S2a, va);
        va = fma2(K2, S1a, va);
        va = fma2(K0, X1a, va);
        ACCa = fma2(BT, abs2(va), ACCa);
        u64t vb = fma2(K4, CSb, K5);
        vb = fma2(K1, MFb, vb);
        vb = fma2(K3, S2b, vb);
        vb = fma2(K2, S1b, vb);
        vb = fma2(K0, X1b, vb);
        ACCb = fma2(BT, abs2(vb), ACCb);
    }

    u64t xsA = fma2(pg[0], X1a, pg[5]);
    xsA = fma2(pg[1], MFa, xsA);
    xsA = fma2(pg[2], S1a, xsA);
    xsA = fma2(pg[3], S2a, xsA);
    xsA = fma2(pg[4], CSa, xsA);
    xsA = add2(xsA, ACCa);
    u64t xsB = fma2(pg[0], X1b, pg[5]);
    xsB = fma2(pg[1], MFb, xsB);
    xsB = fma2(pg[2], S1b, xsB);
    xsB = fma2(pg[3], S2b, xsB);
    xsB = fma2(pg[4], CSb, xsB);
    xsB = add2(xsB, ACCb);

    float xs[4];
    unpack2(xs[0], xs[1], xsA);
    unpack2(xs[2], xs[3], xsB);

    #pragma unroll
    for (int e = 0; e < 4; e++) {
        float v = xs[e];
        int k = 0;
        if (skn[63] < v) k = 64;
        if (skn[k + 31] < v) k += 32;
        if (skn[k + 15] < v) k += 16;
        if (skn[k + 7] < v) k += 8;
        if (skn[k + 3] < v) k += 4;
        if (skn[k + 1] < v) k += 2;
        if (skn[k] < v) k += 1;
        out[base + e * 256] = fmaf(ssl[k], v, sit[k]);
    }
}

// ---------------------------------------------------------------------------
extern "C" void kernel_launch(void* const* d_in, const int* in_sizes, int n_in,
                              void* d_out, int out_size) {
    const float* x     = (const float*)d_in[0];
    const int*   mask  = (const int*)  d_in[1];
    const float* b_fs  = (const float*)d_in[3];
    const float* W_in  = (const float*)d_in[4];
    const float* b_in  = (const float*)d_in[5];
    const float* adj   = (const float*)d_in[6];
    const float* W_gc  = (const float*)d_in[7];
    const float* b_gc  = (const float*)d_in[8];
    const float* W_lo  = (const float*)d_in[9];
    const float* b_lo  = (const float*)d_in[10];
    const float* pre_a = (const float*)d_in[11];
    const float* W_ro  = (const float*)d_in[12];
    const float* b_ro  = (const float*)d_in[13];
    const float* W_o1  = (const float*)d_in[14];
    const float* b_o1  = (const float*)d_in[15];
    const float* W_o2  = (const float*)d_in[16];
    const float* b_o2  = (const float*)d_in[17];
    float* out = (float*)d_out;

    cudaFuncSetAttribute(gemm_mma_kernel,
                         cudaFuncAttributeMaxDynamicSharedMemorySize,
                         GEMM_SMEM);

    // zero the colsum accumulator (graph-capturable memset node)
    void* cs_addr = nullptr;
    cudaGetSymbolAddress(&cs_addr, g_cs);
    cudaMemsetAsync(cs_addr, 0, Ndim * sizeof(float));

    setup_kernel<<<1153, 256>>>(adj, x, mask, b_fs,
                                W_in, b_in, W_gc, b_gc, W_lo, b_lo,
                                pre_a, W_ro, b_ro, W_o1, b_o1, W_o2, b_o2);
    {
        dim3 grid(16, 8, 2);
        gemm_mma_kernel<<<grid, 256, GEMM_SMEM>>>();
    }
    final_kernel<<<512, 256>>>(x, mask, b_fs, out);
}

// round 13
// speedup vs baseline: 1.5246x; 1.1726x over previous
#include <cuda_runtime.h>
#include <cuda_fp16.h>
#include <cstdint>

#define Bdim 8
#define Ndim 1024
#define Tdim 64
#define TOTAL (Bdim*Ndim*Tdim)

typedef unsigned long long u64t;

// scratch (static device memory)
__device__ float g_S[Ndim * 1024];    // K-split half 0
__device__ float g_S2[Ndim * 1024];   // K-split half 1
__device__ float g_cs[Ndim];
__device__ float g_C[6 * 64];
__device__ float g_beta[64];
__device__ float g_gamma[6];
__device__ float g_knots[127];
__device__ float g_slope[65];
__device__ float g_inter[65];
// fp16 operands: [k][col] row-major, 1024 cols (pairs packed in u32)
__device__ __align__(16) uint32_t g_Ah[1024 * 512];
__device__ __align__(16) uint32_t g_Bh[1024 * 512];

// ------------------------------ helpers -----------------------------------
__device__ __forceinline__ uint32_t smem_u32(const void* p) {
    uint32_t a;
    asm("{ .reg .u64 t; cvta.to.shared.u64 t, %1; cvt.u32.u64 %0, t; }"
        : "=r"(a) : "l"(p));
    return a;
}
__device__ __forceinline__ uint32_t pack_f16x2(float lo, float hi) {
    __half2 h = __floats2half2_rn(lo, hi);
    return *(uint32_t*)&h;
}
__device__ __forceinline__ void ldsm_x4_t(uint32_t& r0, uint32_t& r1,
                                          uint32_t& r2, uint32_t& r3,
                                          uint32_t addr) {
    asm volatile("ldmatrix.sync.aligned.m8n8.x4.trans.shared.b16 "
                 "{%0,%1,%2,%3}, [%4];"
                 : "=r"(r0), "=r"(r1), "=r"(r2), "=r"(r3) : "r"(addr));
}
__device__ __forceinline__ void mma16816(float* c, const uint32_t* a,
                                         const uint32_t* b) {
    asm volatile(
        "mma.sync.aligned.m16n8k16.row.col.f32.f16.f16.f32 "
        "{%0,%1,%2,%3}, {%4,%5,%6,%7}, {%8,%9}, {%0,%1,%2,%3};"
        : "+f"(c[0]), "+f"(c[1]), "+f"(c[2]), "+f"(c[3])
        : "r"(a[0]), "r"(a[1]), "r"(a[2]), "r"(a[3]), "r"(b[0]), "r"(b[1]));
}
__device__ __forceinline__ void cp16(uint32_t dst, const void* src) {
    asm volatile("cp.async.cg.shared.global [%0], [%1], 16;"
                 :: "r"(dst), "l"(src) : "memory");
}
// packed f32x2 ops (Blackwell base ISA)
__device__ __forceinline__ u64t fma2(u64t a, u64t b, u64t c) {
    u64t d;
    asm("fma.rn.f32x2 %0, %1, %2, %3;" : "=l"(d) : "l"(a), "l"(b), "l"(c));
    return d;
}
__device__ __forceinline__ u64t add2(u64t a, u64t b) {
    u64t d;
    asm("add.rn.f32x2 %0, %1, %2;" : "=l"(d) : "l"(a), "l"(b));
    return d;
}
__device__ __forceinline__ u64t abs2(u64t a) {
    u64t d;
    asm("and.b64 %0, %1, 0x7FFFFFFF7FFFFFFF;" : "=l"(d) : "l"(a));
    return d;
}
__device__ __forceinline__ u64t pack2(float lo, float hi) {
    u64t d;
    asm("mov.b64 %0, {%1, %2};" : "=l"(d) : "f"(lo), "f"(hi));
    return d;
}
__device__ __forceinline__ void unpack2(float& lo, float& hi, u64t v) {
    asm("mov.b64 {%0, %1}, %2;" : "=f"(lo), "=f"(hi) : "l"(v));
}

// ---------------------------------------------------------------------------
// Kernel 1 (merged setup): grid 1153 x 256.
//   block 0        : coefficient folding + PW-linear tables (parallelized)
//   blocks 1..128  : colsum partial atomics (g_cs pre-zeroed by memset)
//   blocks 129..   : prep (fp16 conversion of adj and R)
// ---------------------------------------------------------------------------
__global__ void __launch_bounds__(256)
setup_kernel(const float* __restrict__ adj,
             const float* __restrict__ x,
             const int*   __restrict__ mask,
             const float* __restrict__ b_fs,
             const float* __restrict__ W_in,
             const float* __restrict__ b_in,
             const float* __restrict__ W_gc,
             const float* __restrict__ b_gc,
             const float* __restrict__ W_lo,
             const float* __restrict__ b_lo,
             const float* __restrict__ prelu_a,
             const float* __restrict__ W_ro,
             const float* __restrict__ b_ro,
             const float* __restrict__ W_o1,
             const float* __restrict__ b_o1,
             const float* __restrict__ W_o2,
             const float* __restrict__ b_o2) {
    __shared__ float w0[64], w1[64], bi[64];
    __shared__ float A[6][64];
    __shared__ float sC[6][64];
    __shared__ float sAl[64];
    __shared__ float kno[64], srt[64];
    __shared__ int   srank[64];
    __shared__ float sw1[64], sb1[64], sw2[64];
    __shared__ float pP[6][4][64];
    __shared__ float sd[64], se[64];
    __shared__ float sbase_sl[2], sbase_in[2];

    const int blk = blockIdx.x;
    const int t = threadIdx.x;

    if (blk == 0) {
        // ---------------- coeff (parallel, 256 threads) ----------------
        const int q = t >> 6;     // k-quarter 0..3
        const int tt = t & 63;    // output index 0..63

        if (t < 64) {
            w0[t] = W_in[t * 66 + 0];
            w1[t] = W_in[t * 66 + 1];
            bi[t] = b_in[t];
        }
        __syncthreads();

        // phase B: A[i][tt] partials over k in [16q, 16q+16)
        {
            float a0 = 0.f, a1 = 0.f, a2 = 0.f, a3 = 0.f, a4 = 0.f, a5 = 0.f;
            #pragma unroll
            for (int kk = 0; kk < 16; kk++) {
                int k = q * 16 + kk;
                float g1 = W_gc[tt * 128 + k];
                float g2 = W_gc[tt * 128 + 64 + k];
                a0 = fmaf(g1, w0[k], a0); a1 = fmaf(g1, w1[k], a1);
                a5 = fmaf(g1, bi[k], a5);
                a2 = fmaf(g2, w0[k], a2); a3 = fmaf(g2, w1[k], a3);
                a4 = fmaf(g2, bi[k], a4);
            }
            pP[0][q][tt] = a0; pP[1][q][tt] = a1; pP[2][q][tt] = a2;
            pP[3][q][tt] = a3; pP[4][q][tt] = a4; pP[5][q][tt] = a5;
        }
        __syncthreads();
        if (t < 64) {
            #pragma unroll
            for (int i = 0; i < 6; i++) {
                float s = pP[i][0][t] + pP[i][1][t] + pP[i][2][t] + pP[i][3][t];
                A[i][t] = (i == 5) ? s + b_gc[t] : s;
            }
        }
        __syncthreads();

        // phase C: fold through W_lo (first 64 cols only)
        {
            float c0 = 0.f, c1 = 0.f, c2 = 0.f, c3 = 0.f, c4 = 0.f, c5 = 0.f;
            #pragma unroll
            for (int kk = 0; kk < 16; kk++) {
                int k = q * 16 + kk;
                float wl = W_lo[tt * 128 + k];
                c0 = fmaf(wl, A[0][k], c0); c1 = fmaf(wl, A[1][k], c1);
                c2 = fmaf(wl, A[2][k], c2); c3 = fmaf(wl, A[3][k], c3);
                c4 = fmaf(wl, A[4][k], c4); c5 = fmaf(wl, A[5][k], c5);
            }
            pP[0][q][tt] = c0; pP[1][q][tt] = c1; pP[2][q][tt] = c2;
            pP[3][q][tt] = c3; pP[4][q][tt] = c4; pP[5][q][tt] = c5;
        }
        __syncthreads();
        if (t < 64) {
            float c[6];
            #pragma unroll
            for (int i = 0; i < 6; i++)
                c[i] = pP[i][0][t] + pP[i][1][t] + pP[i][2][t] + pP[i][3][t];
            c[5] += b_lo[t];
            #pragma unroll
            for (int i = 0; i < 6; i++) { sC[i][t] = c[i]; g_C[i * 64 + t] = c[i]; }
            float a = prelu_a[0];
            float wr = W_ro[t];
            sAl[t] = wr * 0.5f * (1.f + a);
            g_beta[t] = wr * 0.5f * (1.f - a);
            float wv1 = W_o1[t], bv1 = b_o1[t];
            sw1[t] = wv1; sb1[t] = bv1; sw2[t] = W_o2[t];
            kno[t] = (wv1 != 0.f) ? (-bv1 / wv1) : 3.0e38f;
        }
        __syncthreads();

        // gamma on warps 2..7; rank on warps 0..1 (concurrent)
        if (t >= 64 && t < 256) {
            int wi = (t - 64) >> 5;
            if (wi < 6) {
                int l = t & 31;
                float v = fmaf(sAl[l], sC[wi][l], sAl[l + 32] * sC[wi][l + 32]);
                #pragma unroll
                for (int o = 16; o; o >>= 1)
                    v += __shfl_xor_sync(0xffffffff, v, o);
                if (l == 0) g_gamma[wi] = (wi == 5) ? v + b_ro[0] : v;
            }
        } else if (t < 64) {
            float kt = kno[t];
            int r = 0;
            #pragma unroll
            for (int j = 0; j < 64; j++)
                r += (kno[j] < kt) || (kno[j] == kt && j < t);
            srank[t] = r;
            srt[r] = kt;
        }
        __syncthreads();
        if (t < 64) g_knots[t] = srt[t];
        for (int i = 64 + t; i < 127; i += 256) g_knots[i] = 3.2e38f;

        // slope/inter deltas scattered to rank positions + base reductions
        if (t < 64) {
            float w = sw1[t], w2v = sw2[t], b1 = sb1[t];
            int r = srank[t];
            sd[r] = w2v * fabsf(w);
            se[r] = (w > 0.f) ? w2v * b1 : ((w < 0.f) ? -w2v * b1 : 0.f);
            float csl = (w < 0.f) ? w2v * w : 0.f;
            float cin = (w < 0.f) ? w2v * b1
                                  : ((w == 0.f) ? w2v * fmaxf(b1, 0.f) : 0.f);
            #pragma unroll
            for (int o = 16; o; o >>= 1) {
                csl += __shfl_xor_sync(0xffffffff, csl, o);
                cin += __shfl_xor_sync(0xffffffff, cin, o);
            }
            if ((t & 31) == 0) { sbase_sl[t >> 5] = csl; sbase_in[t >> 5] = cin; }
        }
        __syncthreads();
        // inclusive scan within each 32-wide warp over sd/se
        if (t < 64) {
            float dv = sd[t], ev = se[t];
            #pragma unroll
            for (int o = 1; o < 32; o <<= 1) {
                float du = __shfl_up_sync(0xffffffff, dv, o);
                float eu = __shfl_up_sync(0xffffffff, ev, o);
                if ((t & 31) >= o) { dv += du; ev += eu; }
            }
            sd[t] = dv; se[t] = ev;
        }
        __syncthreads();
        if (t < 65) {
            float sl0 = sbase_sl[0] + sbase_sl[1];
            float in0 = sbase_in[0] + sbase_in[1] + b_o2[0];
            float pd = 0.f, pe = 0.f;
            if (t > 0) {
                int r = t - 1;
                pd = sd[r]; pe = se[r];
                if (r >= 32) { pd += sd[31]; pe += se[31]; }
            }
            g_slope[t] = sl0 + pd;
            g_inter[t] = in0 + pe;
        }
    } else if (blk <= 128) {
        // ---------------- colsum partial ----------------
        int bb = blk - 1;
        int m = (bb & 3) * 256 + t;
        int n0 = (bb >> 2) * 32;
        float s = 0.f;
        #pragma unroll 8
        for (int n = n0; n < n0 + 32; n++)
            s += adj[n * Ndim + m];
        atomicAdd(&g_cs[m], s);
    } else {
        // ---------------- prep ----------------
        const int k = blk - 129;
        const float bfs0 = b_fs[0];

        float4 a = *(const float4*)(adj + k * 1024 + t * 4);
        uint2 hp;
        hp.x = pack_f16x2(a.x, a.y);
        hp.y = pack_f16x2(a.z, a.w);
        *(uint2*)&g_Ah[k * 512 + t * 2] = hp;

        int j = 2 * t;
        int b = j >> 6, tt2 = j & 63;
        int gi = b * 65536 + k * 64 + tt2;
        int m0 = mask[gi], m1 = mask[gi + 1];
        float v0 = m0 ? x[gi] : bfs0;
        float v1 = m1 ? x[gi + 1] : bfs0;
        g_Bh[k * 512 + t] = pack_f16x2(v0, v1);
        g_Bh[k * 512 + 256 + t] = pack_f16x2((float)m0, (float)m1);
    }
}

// ---------------------------------------------------------------------------
// Kernel 2: fp16 single-product GEMM, 4-stage cp.async, one sync/iter.
//   CTA: D[128 m, 64 j] over K=512; K-chunk 64, 8 iterations.
//   grid (16 j, 8 m, 2 ksplit) = 256 CTAs, 256 threads, 2 CTAs/SM.
// ---------------------------------------------------------------------------
#define A_STRIDE_B 272
#define B_STRIDE_B 144
#define ST_AH 0
#define ST_BH 17408
#define STAGE_STRIDE 26624
#define NSTAGE 4
#define GEMM_SMEM (NSTAGE * STAGE_STRIDE)   // 106496

__global__ void __launch_bounds__(256, 2)
gemm_mma_kernel() {
    extern __shared__ __align__(16) char smp[];
    const uint32_t sb = smem_u32(smp);

    const int tid  = threadIdx.x;
    const int lane = tid & 31;
    const int wid  = tid >> 5;
    const int warp_m = (wid & 3) * 32;
    const int warp_j = (wid >> 2) * 32;
    const int mcta = blockIdx.y * 128;
    const int bx   = blockIdx.x;
    const int j0   = bx * 64;
    const int kbase = blockIdx.z * 512;

    // ldmatrix per-lane addresses (validated fragment mapping)
    const int aK = (lane & 7) + ((lane & 16) ? 8 : 0);
    const int aM = (lane & 8) ? 8 : 0;
    const int bK = (lane & 7) + ((lane & 8) ? 8 : 0);
    const int bJ = (lane & 16) ? 8 : 0;
    const uint32_t aBase = sb + ST_AH + (uint32_t)(aK * A_STRIDE_B + (warp_m + aM) * 2);
    const uint32_t bBase = sb + ST_BH + (uint32_t)(bK * B_STRIDE_B + (warp_j + bJ) * 2);

    float acc[2][4][4];
    #pragma unroll
    for (int mt = 0; mt < 2; mt++)
        #pragma unroll
        for (int nt = 0; nt < 4; nt++)
            #pragma unroll
            for (int r = 0; r < 4; r++) acc[mt][nt][r] = 0.f;

    // cp.async geometry (K-chunk 64):
    //  A: 64 rows x 16 slots -> 4/thread; B: 64 rows x 8 slots -> 2/thread
    const int arow = tid >> 4, acol = tid & 15;
    const int brow = tid >> 3, bcol = tid & 7;

    auto issue_chunk = [&](int it) {
        const int s = it & (NSTAGE - 1);
        const int k0 = kbase + it * 64;
        const uint32_t stg = sb + s * STAGE_STRIDE;
        #pragma unroll
        for (int i = 0; i < 4; i++) {
            int row = arow + i * 16;
            uint32_t doff = row * A_STRIDE_B + acol * 16;
            size_t goff = (size_t)(k0 + row) * 2048 + mcta * 2 + acol * 16;
            cp16(stg + ST_AH + doff, (const char*)g_Ah + goff);
        }
        #pragma unroll
        for (int i = 0; i < 2; i++) {
            int row = brow + i * 32;
            uint32_t doff = row * B_STRIDE_B + bcol * 16;
            size_t goff = (size_t)(k0 + row) * 2048 + j0 * 2 + bcol * 16;
            cp16(stg + ST_BH + doff, (const char*)g_Bh + goff);
        }
        asm volatile("cp.async.commit_group;" ::: "memory");
    };

    auto compute = [&](int s) {
        const uint32_t aS = aBase + s * STAGE_STRIDE;
        const uint32_t bS = bBase + s * STAGE_STRIDE;
        #pragma unroll
        for (int ks = 0; ks < 4; ks++) {
            uint32_t aKaddr = aS + ks * (16 * A_STRIDE_B);
            uint32_t bKaddr = bS + ks * (16 * B_STRIDE_B);
            uint32_t ah[2][4], bh[2][4];
            ldsm_x4_t(ah[0][0], ah[0][1], ah[0][2], ah[0][3], aKaddr);
            ldsm_x4_t(ah[1][0], ah[1][1], ah[1][2], ah[1][3], aKaddr + 32);
            ldsm_x4_t(bh[0][0], bh[0][1], bh[0][2], bh[0][3], bKaddr);
            ldsm_x4_t(bh[1][0], bh[1][1], bh[1][2], bh[1][3], bKaddr + 32);
            #pragma unroll
            for (int mt = 0; mt < 2; mt++)
                #pragma unroll
                for (int nt = 0; nt < 4; nt++) {
                    const uint32_t* Bh = &bh[nt >> 1][(nt & 1) * 2];
                    mma16816(acc[mt][nt], ah[mt], Bh);
                }
        }
    };

    issue_chunk(0);
    issue_chunk(1);
    issue_chunk(2);
    for (int it = 0; it < 8; ++it) {
        if (it < 6)      asm volatile("cp.async.wait_group 2;" ::: "memory");
        else if (it == 6) asm volatile("cp.async.wait_group 1;" ::: "memory");
        else              asm volatile("cp.async.wait_group 0;" ::: "memory");
        __syncthreads();
        if (it < 5) issue_chunk(it + 3);
        compute(it & (NSTAGE - 1));
    }

    // epilogue
    float* dstbuf = blockIdx.z ? g_S2 : g_S;
    const int gid = lane >> 2, tig = lane & 3;
    const int jw = j0 + warp_j + 2 * tig;
    #pragma unroll
    for (int mt = 0; mt < 2; mt++) {
        int m = mcta + warp_m + mt * 16 + gid;
        #pragma unroll
        for (int nt = 0; nt < 4; nt++) {
            int j = jw + nt * 8;
            *(float2*)&dstbuf[m * 1024 + j] =
                make_float2(acc[mt][nt][0], acc[mt][nt][1]);
            *(float2*)&dstbuf[(m + 8) * 1024 + j] =
                make_float2(acc[mt][nt][2], acc[mt][nt][3]);
        }
    }
}

// ---------------------------------------------------------------------------
// Kernel 3: per-element tail, packed f32x2, E=4, LDS.128 coeff loads.
// 512 blocks x 256.
// ---------------------------------------------------------------------------
__global__ void __launch_bounds__(256)
final_kernel(const float* __restrict__ x,
             const int*   __restrict__ mask,
             const float* __restrict__ b_fs,
             float* __restrict__ out) {
    __shared__ __align__(16) ulonglong2 pcq[64][4];
    __shared__ float skn[127], ssl[65], sit[65];
    __shared__ u64t pg[6];
    int t = threadIdx.x;
    if (t < 64) {
        float c0 = g_C[t],       c1 = g_C[64 + t],  c2 = g_C[128 + t];
        float c3 = g_C[192 + t], c4 = g_C[256 + t], c5 = g_C[320 + t];
        float bt = g_beta[t];
        pcq[t][0] = make_ulonglong2(pack2(c0, c0), pack2(c1, c1));
        pcq[t][1] = make_ulonglong2(pack2(c2, c2), pack2(c3, c3));
        pcq[t][2] = make_ulonglong2(pack2(c4, c4), pack2(c5, c5));
        pcq[t][3] = make_ulonglong2(pack2(bt, bt), 0ull);
    }
    if (t < 127) skn[t] = g_knots[t];
    if (t < 65) { ssl[t] = g_slope[t]; sit[t] = g_inter[t]; }
    if (t < 6) { float g = g_gamma[t]; pg[t] = pack2(g, g); }
    __syncthreads();

    const float bfs0 = b_fs[0];
    const int base = blockIdx.x * 1024 + t;

    float x1[4], mf[4], s1[4], s2[4], csv[4];
    #pragma unroll
    for (int e = 0; e < 4; e++) {
        int idx = base + e * 256;
        int mi = mask[idx];
        float xv = x[idx];
        mf[e] = (float)mi;
        x1[e] = mi ? xv : bfs0;
        int n = (idx >> 6) & (Ndim - 1);
        int b = idx >> 16;
        int tt = idx & 63;
        int j = (b << 6) | tt;
        s1[e] = g_S[n * 1024 + j] + g_S2[n * 1024 + j];
        s2[e] = g_S[n * 1024 + 512 + j] + g_S2[n * 1024 + 512 + j];
        csv[e] = g_cs[n];
    }

    u64t X1a = pack2(x1[0], x1[1]), X1b = pack2(x1[2], x1[3]);
    u64t MFa = pack2(mf[0], mf[1]), MFb = pack2(mf[2], mf[3]);
    u64t S1a = pack2(s1[0], s1[1]), S1b = pack2(s1[2], s1[3]);
    u64t S2a = pack2(s2[0], s2[1]), S2b = pack2(s2[2], s2[3]);
    u64t CSa = pack2(csv[0], csv[1]), CSb = pack2(csv[2], csv[3]);
    u64t ACCa = 0ull, ACCb = 0ull;

    #pragma unroll
    for (int o = 0; o < 64; o++) {
        ulonglong2 q0 = pcq[o][0];
        ulonglong2 q1 = pcq[o][1];
        ulonglong2 q2 = pcq[o][2];
        ulonglong2 q3 = pcq[o][3];
        u64t K0 = q0.x, K1 = q0.y, K2 = q1.x, K3 = q1.y;
        u64t K4 = q2.x, K5 = q2.y, BT = q3.x;
        u64t va = fma2(K4, CSa, K5);
        va = fma2(K1, MFa, va);
        va = fma2(K3, S2a, va);
        va = fma2(K2, S1a, va);
        va = fma2(K0, X1a, va);
        ACCa = fma2(BT, abs2(va), ACCa);
        u64t vb = fma2(K4, CSb, K5);
        vb = fma2(K1, MFb, vb);
        vb = fma2(K3, S2b, vb);
        vb = fma2(K2, S1b, vb);
        vb = fma2(K0, X1b, vb);
        ACCb = fma2(BT, abs2(vb), ACCb);
    }

    u64t xsA = fma2(pg[0], X1a, pg[5]);
    xsA = fma2(pg[1], MFa, xsA);
    xsA = fma2(pg[2], S1a, xsA);
    xsA = fma2(pg[3], S2a, xsA);
    xsA = fma2(pg[4], CSa, xsA);
    xsA = add2(xsA, ACCa);
    u64t xsB = fma2(pg[0], X1b, pg[5]);
    xsB = fma2(pg[1], MFb, xsB);
    xsB = fma2(pg[2], S1b, xsB);
    xsB = fma2(pg[3], S2b, xsB);
    xsB = fma2(pg[4], CSb, xsB);
    xsB = add2(xsB, ACCb);

    float xs[4];
    unpack2(xs[0], xs[1], xsA);
    unpack2(xs[2], xs[3], xsB);

    #pragma unroll
    for (int e = 0; e < 4; e++) {
        float v = xs[e];
        int k = 0;
        if (skn[63] < v) k = 64;
        if (skn[k + 31] < v) k += 32;
        if (skn[k + 15] < v) k += 16;
        if (skn[k + 7] < v) k += 8;
        if (skn[k + 3] < v) k += 4;
        if (skn[k + 1] < v) k += 2;
        if (skn[k] < v) k += 1;
        out[base + e * 256] = fmaf(ssl[k], v, sit[k]);
    }
}

// ---------------------------------------------------------------------------
extern "C" void kernel_launch(void* const* d_in, const int* in_sizes, int n_in,
                              void* d_out, int out_size) {
    const float* x     = (const float*)d_in[0];
    const int*   mask  = (const int*)  d_in[1];
    const float* b_fs  = (const float*)d_in[3];
    const float* W_in  = (const float*)d_in[4];
    const float* b_in  = (const float*)d_in[5];
    const float* adj   = (const float*)d_in[6];
    const float* W_gc  = (const float*)d_in[7];
    const float* b_gc  = (const float*)d_in[8];
    const float* W_lo  = (const float*)d_in[9];
    const float* b_lo  = (const float*)d_in[10];
    const float* pre_a = (const float*)d_in[11];
    const float* W_ro  = (const float*)d_in[12];
    const float* b_ro  = (const float*)d_in[13];
    const float* W_o1  = (const float*)d_in[14];
    const float* b_o1  = (const float*)d_in[15];
    const float* W_o2  = (const float*)d_in[16];
    const float* b_o2  = (const float*)d_in[17];
    float* out = (float*)d_out;

    cudaFuncSetAttribute(gemm_mma_kernel,
                         cudaFuncAttributeMaxDynamicSharedMemorySize,
                         GEMM_SMEM);

    // zero the colsum accumulator (graph-capturable memset node)
    void* cs_addr = nullptr;
    cudaGetSymbolAddress(&cs_addr, g_cs);
    cudaMemsetAsync(cs_addr, 0, Ndim * sizeof(float));

    setup_kernel<<<1153, 256>>>(adj, x, mask, b_fs,
                                W_in, b_in, W_gc, b_gc, W_lo, b_lo,
                                pre_a, W_ro, b_ro, W_o1, b_o1, W_o2, b_o2);
    {
        dim3 grid(16, 8, 2);
        gemm_mma_kernel<<<grid, 256, GEMM_SMEM>>>();
    }
    final_kernel<<<512, 256>>>(x, mask, b_fs, out);
}